// round 11
// baseline (speedup 1.0000x reference)
#include <cuda_runtime.h>
#include <cuda_fp16.h>
#include <stdint.h>

#define BATCH 32768
#define DIM   256
#define NF    4096
#define TOPK  32

// fp16 2-term emulation: hpre = a0*w0 + a0*w1,  a0=fp16(a), w=w0+w1 (fp16 pair)
#define KPA 256     // physical A K (a0 only)
#define KPW 512     // physical W K (w0|w1)

// ---- device scratch (no allocs allowed) ----
static __device__ __align__(1024) __half g_A[(size_t)BATCH * KPA];  // 16.8 MB
static __device__ __align__(1024) __half g_W[(size_t)NF * KPW];     // 4.2 MB
static __device__ __align__(1024) float g_xc[(size_t)BATCH * DIM];  // 33.5 MB
static __device__ __align__(1024) float g_WdecT[(size_t)NF * DIM];  // 4 MB

__device__ __forceinline__ uint32_t smem_u32(const void* p) {
    uint32_t a;
    asm("{ .reg .u64 t; cvta.to.shared.u64 t, %1; cvt.u32.u64 %0, t; }"
        : "=r"(a) : "l"(p));
    return a;
}

// ===========================================================================
// Prep
// ===========================================================================
__global__ void __launch_bounds__(256) prep_a_kernel(
    const float* __restrict__ x, const float* __restrict__ mean,
    const float* __restrict__ stdv, const float* __restrict__ bdec)
{
    int idx = blockIdx.x * 256 + threadIdx.x;
    int d = idx & 255;
    float a = (x[idx] - mean[d]) / stdv[d] - bdec[d];
    g_xc[idx] = a;
    g_A[idx] = __float2half(a);
}

__global__ void __launch_bounds__(256) prep_w_kernel(const float* __restrict__ Wenc)
{
    int idx = blockIdx.x * 256 + threadIdx.x;
    int n = idx >> 8, d = idx & 255;
    float w = Wenc[idx];
    __half w0 = __float2half(w);
    __half w1 = __float2half(w - __half2float(w0));
    size_t base = (size_t)n * KPW;
    g_W[base + d]       = w0;
    g_W[base + 256 + d] = w1;
}

__global__ void transpose_wdec(const float* __restrict__ Wdec)
{
    __shared__ float tile[32][33];
    int n = blockIdx.x * 32 + threadIdx.x;
    int d = blockIdx.y * 32 + threadIdx.y;
    tile[threadIdx.y][threadIdx.x] = Wdec[(size_t)d * NF + n];
    __syncthreads();
    int n2 = blockIdx.x * 32 + threadIdx.y;
    int d2 = blockIdx.y * 32 + threadIdx.x;
    g_WdecT[(size_t)n2 * DIM + d2] = tile[threadIdx.x][threadIdx.y];
}

// ===========================================================================
// mma.sync fp16 GEMM (identical to the validated 355us version):
//   hpre = a0*w0 + a0*w1 + benc over 8 logical K64-chunks
// CTA tile 128x128, warps 4(M)x2(N), 3-stage cp.async, fully unrolled.
// ===========================================================================
#define GM 128
#define GN 128
#define NCH 8
#define ATILE (GM * 128)             // 16384 B
#define BTILE (GN * 128)             // 16384 B
#define STAGE (ATILE + BTILE)        // 32768 B
#define DSMEM (3 * STAGE)            // 98304 B

__global__ void __launch_bounds__(256, 2) gemm_kernel(
    const float* __restrict__ benc, float* __restrict__ hpre)
{
    extern __shared__ char dsm[];
    const uint32_t sb = smem_u32(dsm);
    const int tid = threadIdx.x;
    const int wid = tid >> 5, lane = tid & 31;
    const int wm = wid & 3;          // 0..3  (M)
    const int wn = wid >> 2;         // 0..1  (N)

    const int m0 = blockIdx.y * GM;
    const int n0 = blockIdx.x * GN;
    const char* Abase = (const char*)g_A + (size_t)m0 * (KPA * 2);
    const char* Bbase = (const char*)g_W + (size_t)n0 * (KPW * 2);

    // 128B chunk-rows; 16B piece i of row r lands at piece (i ^ (r&7))
    auto load_chunk = [&](int c, uint32_t stagebase) {
        const char* Ag = Abase + (c & 3) * 128;
#pragma unroll
        for (int q = 0; q < 4; q++) {
            int p = tid + 256 * q; int row = p >> 3, i = p & 7;
            uint32_t sw = (uint32_t)(row * 128) + (uint32_t)((i ^ (row & 7)) * 16);
            asm volatile("cp.async.cg.shared.global [%0], [%1], 16;"
                :: "r"(stagebase + sw), "l"(Ag + (size_t)row * (KPA * 2) + i * 16));
        }
        const char* Bg = Bbase + c * 128;
        const uint32_t bb = stagebase + ATILE;
#pragma unroll
        for (int q = 0; q < 4; q++) {
            int p = tid + 256 * q; int row = p >> 3, i = p & 7;
            uint32_t sw = (uint32_t)(row * 128) + (uint32_t)((i ^ (row & 7)) * 16);
            asm volatile("cp.async.cg.shared.global [%0], [%1], 16;"
                :: "r"(bb + sw), "l"(Bg + (size_t)row * (KPW * 2) + i * 16));
        }
    };

    load_chunk(0, sb);
    asm volatile("cp.async.commit_group;" ::: "memory");
    load_chunk(1, sb + STAGE);
    asm volatile("cp.async.commit_group;" ::: "memory");

    float acc[2][8][4];
#pragma unroll
    for (int a = 0; a < 2; a++)
#pragma unroll
        for (int b = 0; b < 8; b++)
#pragma unroll
            for (int cc = 0; cc < 4; cc++) acc[a][b][cc] = 0.f;

#pragma unroll
    for (int c = 0; c < NCH; c++) {
        if (c < NCH - 1) { asm volatile("cp.async.wait_group 1;" ::: "memory"); }
        else             { asm volatile("cp.async.wait_group 0;" ::: "memory"); }
        __syncthreads();
        if (c + 2 < NCH) {
            load_chunk(c + 2, sb + ((c + 2) % 3) * STAGE);
            asm volatile("cp.async.commit_group;" ::: "memory");
        }

        const uint32_t As = sb + (c % 3) * STAGE;
        const uint32_t Bs = As + ATILE;

#pragma unroll
        for (int ks = 0; ks < 4; ks++) {          // 4 x k16 per 64-chunk
            uint32_t aF[2][4], bF[8][2];
#pragma unroll
            for (int mt = 0; mt < 2; mt++) {
                int row = wm * 32 + mt * 16 + (lane & 15);
                int i = ks * 2 + (lane >> 4);
                uint32_t addr = As + row * 128 + ((i ^ (row & 7)) * 16);
                asm volatile("ldmatrix.sync.aligned.m8n8.x4.shared.b16 {%0,%1,%2,%3}, [%4];"
                    : "=r"(aF[mt][0]), "=r"(aF[mt][1]), "=r"(aF[mt][2]), "=r"(aF[mt][3])
                    : "r"(addr));
            }
#pragma unroll
            for (int nt4 = 0; nt4 < 4; nt4++) {
                int row = wn * 64 + nt4 * 16 + (lane & 15);
                int i = ks * 2 + (lane >> 4);
                uint32_t addr = Bs + row * 128 + ((i ^ (row & 7)) * 16);
                uint32_t r0, r1, r2, r3;
                asm volatile("ldmatrix.sync.aligned.m8n8.x4.shared.b16 {%0,%1,%2,%3}, [%4];"
                    : "=r"(r0), "=r"(r1), "=r"(r2), "=r"(r3) : "r"(addr));
                bF[nt4 * 2][0] = r0;  bF[nt4 * 2][1] = r2;
                bF[nt4 * 2 + 1][0] = r1; bF[nt4 * 2 + 1][1] = r3;
            }
#pragma unroll
            for (int mt = 0; mt < 2; mt++)
#pragma unroll
                for (int nt = 0; nt < 8; nt++)
                    asm volatile(
                        "mma.sync.aligned.m16n8k16.row.col.f32.f16.f16.f32 "
                        "{%0,%1,%2,%3}, {%4,%5,%6,%7}, {%8,%9}, {%0,%1,%2,%3};"
                        : "+f"(acc[mt][nt][0]), "+f"(acc[mt][nt][1]),
                          "+f"(acc[mt][nt][2]), "+f"(acc[mt][nt][3])
                        : "r"(aF[mt][0]), "r"(aF[mt][1]), "r"(aF[mt][2]), "r"(aF[mt][3]),
                          "r"(bF[nt][0]), "r"(bF[nt][1]));
        }
    }

    // Epilogue: +b_enc, write h_pre
    const int g = lane >> 2, tg = lane & 3;
#pragma unroll
    for (int mt = 0; mt < 2; mt++) {
        const int m = m0 + wm * 32 + mt * 16 + g;
#pragma unroll
        for (int nt = 0; nt < 8; nt++) {
            const int n = n0 + wn * 64 + nt * 8 + tg * 2;
            float2 be = *(const float2*)(benc + n);
            float2 o0, o1;
            o0.x = acc[mt][nt][0] + be.x; o0.y = acc[mt][nt][1] + be.y;
            o1.x = acc[mt][nt][2] + be.x; o1.y = acc[mt][nt][3] + be.y;
            *(float2*)(hpre + (size_t)m * NF + n) = o0;
            *(float2*)(hpre + (size_t)(m + 8) * NF + n) = o1;
        }
    }
}

// ===========================================================================
// Top-K with EXACT selection. 512 threads/row, 8 keys/thread (~32 regs ->
// 4 CTAs/SM = 100% occupancy). Plain shared histogram; pass 1 positives-only
// with sentinel fallback; cut lowered one 16-bit bin; candidates recomputed
// exactly in fp32; tail split: warps 0-7 decode, warps 8-15 stream h_sparse.
// ===========================================================================
#define TBLK 512
#define CCAP 96
#define BSENT 0xFFFFFFFFu

__global__ void __launch_bounds__(TBLK) topk_decode_kernel(
    const float* __restrict__ hpre,
    const float* __restrict__ Wenc,
    const float* __restrict__ benc,
    const float* __restrict__ bdec,
    float* __restrict__ hsp,
    float* __restrict__ xhat)
{
    __shared__ float srow[NF];          // 16 KB: full h_sparse row
    __shared__ unsigned hist[256];
    __shared__ float sxc[256];
    __shared__ unsigned sh_byte, sh_excl;
    __shared__ int sh_c;
    __shared__ int   cidx[CCAP];
    __shared__ float hex[CCAP];
    __shared__ int   sseli[TOPK];
    __shared__ float sselv[TOPK];

    const int row = blockIdx.x;
    const int tid = threadIdx.x;
    const int wid = tid >> 5, lane = tid & 31;
    const float* rp = hpre + (size_t)row * NF;

    if (tid < 256) sxc[tid] = g_xc[(size_t)row * DIM + tid];

    // zero the smem h_sparse row (512 threads x 2 float4)
    {
        const float4 z4 = make_float4(0.f, 0.f, 0.f, 0.f);
        float4* s4 = (float4*)srow;
        s4[tid] = z4;
        s4[tid + TBLK] = z4;
    }

    // element i -> column (tid*4 + (i&3) + (i>>2)*2048); keys only
    unsigned key[8];
    const uint4* rp4 = (const uint4*)rp + tid;
#pragma unroll
    for (int i4 = 0; i4 < 2; i4++) {
        uint4 t = rp4[i4 * TBLK];
        key[i4 * 4 + 0] = t.x ^ ((unsigned)(((int)t.x) >> 31) | 0x80000000u);
        key[i4 * 4 + 1] = t.y ^ ((unsigned)(((int)t.y) >> 31) | 0x80000000u);
        key[i4 * 4 + 2] = t.z ^ ((unsigned)(((int)t.z) >> 31) | 0x80000000u);
        key[i4 * 4 + 3] = t.w ^ ((unsigned)(((int)t.w) >> 31) | 0x80000000u);
    }

    unsigned rem = TOPK;
    unsigned prefix = 0;

    // find the 8-bit bin of the rem-th largest in hist[] (from-the-top scan)
    auto scan_select = [&]() {
        __syncthreads();
        if (tid < 32) {
            unsigned h[8], tot = 0;
#pragma unroll
            for (int k = 0; k < 8; k++) { h[k] = hist[tid * 8 + k]; tot += h[k]; }
            unsigned suf = tot;
#pragma unroll
            for (int o = 1; o < 32; o <<= 1) {
                unsigned u = __shfl_down_sync(0xffffffffu, suf, o);
                if (tid + o < 32) suf += u;
            }
            unsigned excl = suf - tot;
#pragma unroll
            for (int k = 7; k >= 0; k--) {
                unsigned incl = excl + h[k];
                if (excl < rem && incl >= rem) { sh_byte = (unsigned)(tid * 8 + k); sh_excl = excl; }
                excl = incl;
            }
        }
        __syncthreads();
    };

    // ---- pass 1: bits [31:24], positives only (keys >= 0x80000000) ----
    if (tid < 256) hist[tid] = 0;
    if (tid == 0) sh_byte = BSENT;
    __syncthreads();
#pragma unroll
    for (int i = 0; i < 8; i++)
        if (key[i] & 0x80000000u) atomicAdd(&hist[key[i] >> 24], 1u);
    scan_select();
    if (sh_byte == BSENT) {
        // rare fallback: fewer than TOPK positive values in this row
        __syncthreads();
        if (tid < 256) hist[tid] = 0;
        __syncthreads();
#pragma unroll
        for (int i = 0; i < 8; i++) atomicAdd(&hist[key[i] >> 24], 1u);
        scan_select();
    }
    prefix = sh_byte;
    rem -= sh_excl;
    __syncthreads();

    // ---- pass 2: bits [23:16] among prefix matches ----
    if (tid < 256) hist[tid] = 0;
    if (tid == 0) sh_c = 0;
    __syncthreads();
#pragma unroll
    for (int i = 0; i < 8; i++)
        if ((key[i] >> 24) == prefix) atomicAdd(&hist[(key[i] >> 16) & 255u], 1u);
    scan_select();
    unsigned cut = ((prefix << 8) | sh_byte) << 16;
    cut = (cut >= (1u << 16)) ? cut - (1u << 16) : 0u;   // one-bin safety margin

    // ---- gather candidates (all keys >= lowered cut) ----
#pragma unroll
    for (int i = 0; i < 8; i++) {
        if (key[i] >= cut) {
            int p = atomicAdd(&sh_c, 1);
            if (p < CCAP) cidx[p] = (tid << 2) + (i & 3) + ((i >> 2) << 11);
        }
    }
    __syncthreads();
    const int C = (sh_c < CCAP) ? sh_c : CCAP;

    // ---- exact fp32 recompute of candidate dots (16 warps) ----
    for (int j = wid; j < C; j += 16) {
        const float* wr = Wenc + (size_t)cidx[j] * DIM;
        float p = 0.f;
#pragma unroll
        for (int d = 0; d < DIM; d += 32) p = fmaf(sxc[d + lane], wr[d + lane], p);
#pragma unroll
        for (int o = 16; o > 0; o >>= 1) p += __shfl_xor_sync(0xffffffffu, p, o);
        if (lane == 0) hex[j] = p + benc[cidx[j]];
    }
    __syncthreads();

    // ---- rank (value desc, index asc), select top-32, scatter into smem row ----
    if (tid < C) {
        const float my = hex[tid];
        const int myi = cidx[tid];
        int rank = 0;
        for (int j = 0; j < C; j++) {
            float h = hex[j];
            rank += (h > my) || (h == my && cidx[j] < myi);
        }
        if (rank < TOPK) {
            sselv[rank] = my;
            sseli[rank] = myi;
            srow[myi] = my;
        }
    }
    __syncthreads();

    // ---- parallel tail: warps 0-7 decode, warps 8-15 stream h_sparse ----
    if (tid < 256) {
        float acc = bdec[tid];
#pragma unroll
        for (int j = 0; j < TOPK; j++)
            acc = fmaf(sselv[j], g_WdecT[(size_t)sseli[j] * DIM + tid], acc);
        xhat[(size_t)row * DIM + tid] = acc;
    } else {
        const int t = tid - 256;                       // 0..255
        float4* hp4 = (float4*)(hsp + (size_t)row * NF);
        const float4* s4 = (const float4*)srow;
#pragma unroll
        for (int j = 0; j < 4; j++) __stcs(hp4 + t + 256 * j, s4[t + 256 * j]);
    }
}

// ===========================================================================
extern "C" void kernel_launch(void* const* d_in, const int* in_sizes, int n_in,
                              void* d_out, int out_size)
{
    const float* x    = (const float*)d_in[0];
    const float* Wenc = (const float*)d_in[1];
    const float* benc = (const float*)d_in[2];
    const float* Wdec = (const float*)d_in[3];
    const float* bdec = (const float*)d_in[4];
    const float* mean = (const float*)d_in[5];
    const float* stdv = (const float*)d_in[6];

    float* out  = (float*)d_out;
    float* xhat = out;                               // (B, D)
    float* hsp  = out + (size_t)BATCH * DIM;         // (B, N)
    float* hpre = hsp + (size_t)BATCH * NF;          // (B, N)

    prep_a_kernel<<<BATCH * DIM / 256, 256>>>(x, mean, stdv, bdec);
    prep_w_kernel<<<NF * DIM / 256, 256>>>(Wenc);

    dim3 tb(32, 32);
    dim3 tg(NF / 32, DIM / 32);
    transpose_wdec<<<tg, tb>>>(Wdec);

    cudaFuncSetAttribute(gemm_kernel,
                         cudaFuncAttributeMaxDynamicSharedMemorySize, DSMEM);
    dim3 gg(NF / GN, BATCH / GM);
    gemm_kernel<<<gg, 256, DSMEM>>>(benc, hpre);

    topk_decode_kernel<<<BATCH, TBLK>>>(hpre, Wenc, benc, bdec, hsp, xhat);
}

// round 12
// speedup vs baseline: 1.2454x; 1.2454x over previous
#include <cuda_runtime.h>
#include <cuda_fp16.h>
#include <stdint.h>

#define BATCH 32768
#define DIM   256
#define NF    4096
#define TOPK  32

// 1-term fp16 GEMM: hpre ~= a0*w0 (K=256). Values only need ~1e-3 accuracy;
// selection is exact via fp32 candidate recompute with a lowered cut.
#define KPA 256
#define KPW 256

// ---- device scratch (no allocs allowed) ----
static __device__ __align__(1024) __half g_A[(size_t)BATCH * KPA];  // 16.8 MB
static __device__ __align__(1024) __half g_W[(size_t)NF * KPW];     // 2.1 MB
static __device__ __align__(1024) float g_xc[(size_t)BATCH * DIM];  // 33.5 MB
static __device__ __align__(1024) float g_WdecT[(size_t)NF * DIM];  // 4 MB

__device__ __forceinline__ uint32_t smem_u32(const void* p) {
    uint32_t a;
    asm("{ .reg .u64 t; cvta.to.shared.u64 t, %1; cvt.u32.u64 %0, t; }"
        : "=r"(a) : "l"(p));
    return a;
}

// ===========================================================================
// Prep
// ===========================================================================
__global__ void __launch_bounds__(256) prep_a_kernel(
    const float* __restrict__ x, const float* __restrict__ mean,
    const float* __restrict__ stdv, const float* __restrict__ bdec)
{
    int idx = blockIdx.x * 256 + threadIdx.x;
    int d = idx & 255;
    float a = (x[idx] - mean[d]) / stdv[d] - bdec[d];
    g_xc[idx] = a;
    g_A[idx] = __float2half(a);
}

__global__ void __launch_bounds__(256) prep_w_kernel(const float* __restrict__ Wenc)
{
    int idx = blockIdx.x * 256 + threadIdx.x;
    g_W[idx] = __float2half(Wenc[idx]);
}

__global__ void transpose_wdec(const float* __restrict__ Wdec)
{
    __shared__ float tile[32][33];
    int n = blockIdx.x * 32 + threadIdx.x;
    int d = blockIdx.y * 32 + threadIdx.y;
    tile[threadIdx.y][threadIdx.x] = Wdec[(size_t)d * NF + n];
    __syncthreads();
    int n2 = blockIdx.x * 32 + threadIdx.y;
    int d2 = blockIdx.y * 32 + threadIdx.x;
    g_WdecT[(size_t)n2 * DIM + d2] = tile[threadIdx.x][threadIdx.y];
}

// ===========================================================================
// mma.sync fp16 GEMM: hpre = a0*w0 + benc over 4 K64-chunks.
// CTA tile 128x128, warps 4(M)x2(N), 3-stage cp.async, fully unrolled.
// (Same validated structure as the 355us 8-chunk version, half the chunks.)
// ===========================================================================
#define GM 128
#define GN 128
#define NCH 4
#define ATILE (GM * 128)             // 16384 B
#define BTILE (GN * 128)             // 16384 B
#define STAGE (ATILE + BTILE)        // 32768 B
#define DSMEM (3 * STAGE)            // 98304 B

__global__ void __launch_bounds__(256, 2) gemm_kernel(
    const float* __restrict__ benc, float* __restrict__ hpre)
{
    extern __shared__ char dsm[];
    const uint32_t sb = smem_u32(dsm);
    const int tid = threadIdx.x;
    const int wid = tid >> 5, lane = tid & 31;
    const int wm = wid & 3;          // 0..3  (M)
    const int wn = wid >> 2;         // 0..1  (N)

    const int m0 = blockIdx.y * GM;
    const int n0 = blockIdx.x * GN;
    const char* Abase = (const char*)g_A + (size_t)m0 * (KPA * 2);
    const char* Bbase = (const char*)g_W + (size_t)n0 * (KPW * 2);

    // 128B chunk-rows; 16B piece i of row r lands at piece (i ^ (r&7))
    auto load_chunk = [&](int c, uint32_t stagebase) {
        const char* Ag = Abase + c * 128;
#pragma unroll
        for (int q = 0; q < 4; q++) {
            int p = tid + 256 * q; int row = p >> 3, i = p & 7;
            uint32_t sw = (uint32_t)(row * 128) + (uint32_t)((i ^ (row & 7)) * 16);
            asm volatile("cp.async.cg.shared.global [%0], [%1], 16;"
                :: "r"(stagebase + sw), "l"(Ag + (size_t)row * (KPA * 2) + i * 16));
        }
        const char* Bg = Bbase + c * 128;
        const uint32_t bb = stagebase + ATILE;
#pragma unroll
        for (int q = 0; q < 4; q++) {
            int p = tid + 256 * q; int row = p >> 3, i = p & 7;
            uint32_t sw = (uint32_t)(row * 128) + (uint32_t)((i ^ (row & 7)) * 16);
            asm volatile("cp.async.cg.shared.global [%0], [%1], 16;"
                :: "r"(bb + sw), "l"(Bg + (size_t)row * (KPW * 2) + i * 16));
        }
    };

    load_chunk(0, sb);
    asm volatile("cp.async.commit_group;" ::: "memory");
    load_chunk(1, sb + STAGE);
    asm volatile("cp.async.commit_group;" ::: "memory");

    float acc[2][8][4];
#pragma unroll
    for (int a = 0; a < 2; a++)
#pragma unroll
        for (int b = 0; b < 8; b++)
#pragma unroll
            for (int cc = 0; cc < 4; cc++) acc[a][b][cc] = 0.f;

#pragma unroll
    for (int c = 0; c < NCH; c++) {
        if (c < NCH - 1) { asm volatile("cp.async.wait_group 1;" ::: "memory"); }
        else             { asm volatile("cp.async.wait_group 0;" ::: "memory"); }
        __syncthreads();
        if (c + 2 < NCH) {
            load_chunk(c + 2, sb + ((c + 2) % 3) * STAGE);
            asm volatile("cp.async.commit_group;" ::: "memory");
        }

        const uint32_t As = sb + (c % 3) * STAGE;
        const uint32_t Bs = As + ATILE;

#pragma unroll
        for (int ks = 0; ks < 4; ks++) {          // 4 x k16 per 64-chunk
            uint32_t aF[2][4], bF[8][2];
#pragma unroll
            for (int mt = 0; mt < 2; mt++) {
                int row = wm * 32 + mt * 16 + (lane & 15);
                int i = ks * 2 + (lane >> 4);
                uint32_t addr = As + row * 128 + ((i ^ (row & 7)) * 16);
                asm volatile("ldmatrix.sync.aligned.m8n8.x4.shared.b16 {%0,%1,%2,%3}, [%4];"
                    : "=r"(aF[mt][0]), "=r"(aF[mt][1]), "=r"(aF[mt][2]), "=r"(aF[mt][3])
                    : "r"(addr));
            }
#pragma unroll
            for (int nt4 = 0; nt4 < 4; nt4++) {
                int row = wn * 64 + nt4 * 16 + (lane & 15);
                int i = ks * 2 + (lane >> 4);
                uint32_t addr = Bs + row * 128 + ((i ^ (row & 7)) * 16);
                uint32_t r0, r1, r2, r3;
                asm volatile("ldmatrix.sync.aligned.m8n8.x4.shared.b16 {%0,%1,%2,%3}, [%4];"
                    : "=r"(r0), "=r"(r1), "=r"(r2), "=r"(r3) : "r"(addr));
                bF[nt4 * 2][0] = r0;  bF[nt4 * 2][1] = r2;
                bF[nt4 * 2 + 1][0] = r1; bF[nt4 * 2 + 1][1] = r3;
            }
#pragma unroll
            for (int mt = 0; mt < 2; mt++)
#pragma unroll
                for (int nt = 0; nt < 8; nt++)
                    asm volatile(
                        "mma.sync.aligned.m16n8k16.row.col.f32.f16.f16.f32 "
                        "{%0,%1,%2,%3}, {%4,%5,%6,%7}, {%8,%9}, {%0,%1,%2,%3};"
                        : "+f"(acc[mt][nt][0]), "+f"(acc[mt][nt][1]),
                          "+f"(acc[mt][nt][2]), "+f"(acc[mt][nt][3])
                        : "r"(aF[mt][0]), "r"(aF[mt][1]), "r"(aF[mt][2]), "r"(aF[mt][3]),
                          "r"(bF[nt][0]), "r"(bF[nt][1]));
        }
    }

    // Epilogue: +b_enc, write h_pre
    const int g = lane >> 2, tg = lane & 3;
#pragma unroll
    for (int mt = 0; mt < 2; mt++) {
        const int m = m0 + wm * 32 + mt * 16 + g;
#pragma unroll
        for (int nt = 0; nt < 8; nt++) {
            const int n = n0 + wn * 64 + nt * 8 + tg * 2;
            float2 be = *(const float2*)(benc + n);
            float2 o0, o1;
            o0.x = acc[mt][nt][0] + be.x; o0.y = acc[mt][nt][1] + be.y;
            o1.x = acc[mt][nt][2] + be.x; o1.y = acc[mt][nt][3] + be.y;
            *(float2*)(hpre + (size_t)m * NF + n) = o0;
            *(float2*)(hpre + (size_t)(m + 8) * NF + n) = o1;
        }
    }
}

// ===========================================================================
// Top-K with EXACT selection (best-measured round-10 version, unchanged).
// Keys only; plain shared histogram; pass 1 positives-only with sentinel
// fallback; cut lowered one 16-bit bin; candidates recomputed exactly in
// fp32; full h_sparse row built in smem and streamed out.
// ===========================================================================
#define CCAP 96
#define BSENT 0xFFFFFFFFu

__global__ void __launch_bounds__(256) topk_decode_kernel(
    const float* __restrict__ hpre,
    const float* __restrict__ Wenc,
    const float* __restrict__ benc,
    const float* __restrict__ bdec,
    float* __restrict__ hsp,
    float* __restrict__ xhat)
{
    __shared__ float srow[NF];          // 16 KB: full h_sparse row
    __shared__ unsigned hist[256];
    __shared__ float sxc[256];
    __shared__ unsigned sh_byte, sh_excl;
    __shared__ int sh_c;
    __shared__ int   cidx[CCAP];
    __shared__ float hex[CCAP];
    __shared__ int   sseli[TOPK];
    __shared__ float sselv[TOPK];

    const int row = blockIdx.x;
    const int tid = threadIdx.x;
    const int wid = tid >> 5, lane = tid & 31;
    const float* rp = hpre + (size_t)row * NF;

    sxc[tid] = g_xc[(size_t)row * DIM + tid];

    // zero the smem h_sparse row
    {
        const float4 z4 = make_float4(0.f, 0.f, 0.f, 0.f);
        float4* s4 = (float4*)srow;
#pragma unroll
        for (int j = 0; j < 4; j++) s4[tid + 256 * j] = z4;
    }

    // element i -> column (tid*4 + (i&3) + (i>>2)*1024); keys only
    unsigned key[16];
    const uint4* rp4 = (const uint4*)rp + tid;
#pragma unroll
    for (int i4 = 0; i4 < 4; i4++) {
        uint4 t = rp4[i4 * 256];
        key[i4 * 4 + 0] = t.x ^ ((unsigned)(((int)t.x) >> 31) | 0x80000000u);
        key[i4 * 4 + 1] = t.y ^ ((unsigned)(((int)t.y) >> 31) | 0x80000000u);
        key[i4 * 4 + 2] = t.z ^ ((unsigned)(((int)t.z) >> 31) | 0x80000000u);
        key[i4 * 4 + 3] = t.w ^ ((unsigned)(((int)t.w) >> 31) | 0x80000000u);
    }

    unsigned rem = TOPK;
    unsigned prefix = 0;

    // find the 8-bit bin of the rem-th largest in hist[] (from-the-top scan)
    auto scan_select = [&]() {
        __syncthreads();
        if (tid < 32) {
            unsigned h[8], tot = 0;
#pragma unroll
            for (int k = 0; k < 8; k++) { h[k] = hist[tid * 8 + k]; tot += h[k]; }
            unsigned suf = tot;
#pragma unroll
            for (int o = 1; o < 32; o <<= 1) {
                unsigned u = __shfl_down_sync(0xffffffffu, suf, o);
                if (tid + o < 32) suf += u;
            }
            unsigned excl = suf - tot;
#pragma unroll
            for (int k = 7; k >= 0; k--) {
                unsigned incl = excl + h[k];
                if (excl < rem && incl >= rem) { sh_byte = (unsigned)(tid * 8 + k); sh_excl = excl; }
                excl = incl;
            }
        }
        __syncthreads();
    };

    // ---- pass 1: bits [31:24], positives only (keys >= 0x80000000) ----
    hist[tid] = 0;
    if (tid == 0) sh_byte = BSENT;
    __syncthreads();
#pragma unroll
    for (int i = 0; i < 16; i++)
        if (key[i] & 0x80000000u) atomicAdd(&hist[key[i] >> 24], 1u);
    scan_select();
    if (sh_byte == BSENT) {
        // rare fallback: fewer than TOPK positive values in this row
        __syncthreads();
        hist[tid] = 0;
        __syncthreads();
#pragma unroll
        for (int i = 0; i < 16; i++) atomicAdd(&hist[key[i] >> 24], 1u);
        scan_select();
    }
    prefix = sh_byte;
    rem -= sh_excl;
    __syncthreads();

    // ---- pass 2: bits [23:16] among prefix matches ----
    hist[tid] = 0;
    if (tid == 0) sh_c = 0;
    __syncthreads();
#pragma unroll
    for (int i = 0; i < 16; i++)
        if ((key[i] >> 24) == prefix) atomicAdd(&hist[(key[i] >> 16) & 255u], 1u);
    scan_select();
    unsigned cut = ((prefix << 8) | sh_byte) << 16;
    cut = (cut >= (1u << 16)) ? cut - (1u << 16) : 0u;   // one-bin safety margin

    // ---- gather candidates (all keys >= lowered cut) ----
#pragma unroll
    for (int i = 0; i < 16; i++) {
        if (key[i] >= cut) {
            int p = atomicAdd(&sh_c, 1);
            if (p < CCAP) cidx[p] = (tid << 2) + (i & 3) + ((i >> 2) << 10);
        }
    }
    __syncthreads();
    const int C = (sh_c < CCAP) ? sh_c : CCAP;

    // ---- exact fp32 recompute of candidate dots ----
    for (int j = wid; j < C; j += 8) {
        const float* wr = Wenc + (size_t)cidx[j] * DIM;
        float p = 0.f;
#pragma unroll
        for (int d = 0; d < DIM; d += 32) p = fmaf(sxc[d + lane], wr[d + lane], p);
#pragma unroll
        for (int o = 16; o > 0; o >>= 1) p += __shfl_xor_sync(0xffffffffu, p, o);
        if (lane == 0) hex[j] = p + benc[cidx[j]];
    }
    __syncthreads();

    // ---- rank (value desc, index asc), select top-32, scatter into smem row ----
    if (tid < C) {
        const float my = hex[tid];
        const int myi = cidx[tid];
        int rank = 0;
        for (int j = 0; j < C; j++) {
            float h = hex[j];
            rank += (h > my) || (h == my && cidx[j] < myi);
        }
        if (rank < TOPK) {
            sselv[rank] = my;
            sseli[rank] = myi;
            srow[myi] = my;
        }
    }
    __syncthreads();

    // ---- stream the full h_sparse row out (streaming stores) ----
    {
        float4* hp4 = (float4*)(hsp + (size_t)row * NF);
        const float4* s4 = (const float4*)srow;
#pragma unroll
        for (int j = 0; j < 4; j++) __stcs(hp4 + tid + 256 * j, s4[tid + 256 * j]);
    }

    // ---- sparse decode from exact values ----
    float acc = bdec[tid];
#pragma unroll
    for (int j = 0; j < TOPK; j++)
        acc = fmaf(sselv[j], g_WdecT[(size_t)sseli[j] * DIM + tid], acc);
    xhat[(size_t)row * DIM + tid] = acc;
}

// ===========================================================================
extern "C" void kernel_launch(void* const* d_in, const int* in_sizes, int n_in,
                              void* d_out, int out_size)
{
    const float* x    = (const float*)d_in[0];
    const float* Wenc = (const float*)d_in[1];
    const float* benc = (const float*)d_in[2];
    const float* Wdec = (const float*)d_in[3];
    const float* bdec = (const float*)d_in[4];
    const float* mean = (const float*)d_in[5];
    const float* stdv = (const float*)d_in[6];

    float* out  = (float*)d_out;
    float* xhat = out;                               // (B, D)
    float* hsp  = out + (size_t)BATCH * DIM;         // (B, N)
    float* hpre = hsp + (size_t)BATCH * NF;          // (B, N)

    prep_a_kernel<<<BATCH * DIM / 256, 256>>>(x, mean, stdv, bdec);
    prep_w_kernel<<<NF * DIM / 256, 256>>>(Wenc);

    dim3 tb(32, 32);
    dim3 tg(NF / 32, DIM / 32);
    transpose_wdec<<<tg, tb>>>(Wdec);

    cudaFuncSetAttribute(gemm_kernel,
                         cudaFuncAttributeMaxDynamicSharedMemorySize, DSMEM);
    dim3 gg(NF / GN, BATCH / GM);
    gemm_kernel<<<gg, 256, DSMEM>>>(benc, hpre);

    topk_decode_kernel<<<BATCH, 256>>>(hpre, Wenc, benc, bdec, hsp, xhat);
}

// round 13
// speedup vs baseline: 1.2664x; 1.0169x over previous
#include <cuda_runtime.h>
#include <cuda_fp16.h>
#include <stdint.h>

#define BATCH 32768
#define DIM   256
#define NF    4096
#define TOPK  32

// 1-term fp16 GEMM: hpre ~= a0*w0 (K=256). Values only need ~1e-3 accuracy;
// selection is exact via fp32 candidate recompute with a lowered cut.
#define KPA 256
#define KPW 256

// ---- device scratch (no allocs allowed) ----
static __device__ __align__(1024) __half g_A[(size_t)BATCH * KPA];      // 16.8 MB
static __device__ __align__(1024) __half g_W[(size_t)NF * KPW];         // 2.1 MB
static __device__ __align__(1024) float g_xc[(size_t)BATCH * DIM];      // 33.5 MB
static __device__ __align__(1024) float g_WdecT[(size_t)NF * DIM];      // 4 MB
static __device__ __align__(1024) uint16_t g_hkey[(size_t)BATCH * NF];  // 268 MB

__device__ __forceinline__ uint32_t smem_u32(const void* p) {
    uint32_t a;
    asm("{ .reg .u64 t; cvta.to.shared.u64 t, %1; cvt.u32.u64 %0, t; }"
        : "=r"(a) : "l"(p));
    return a;
}

// top 16 bits of the order-preserving key transform
__device__ __forceinline__ uint32_t key16(float v) {
    uint32_t u = __float_as_uint(v);
    uint32_t k = u ^ ((uint32_t)(((int)u) >> 31) | 0x80000000u);
    return k >> 16;
}

// ===========================================================================
// Prep
// ===========================================================================
__global__ void __launch_bounds__(256) prep_a_kernel(
    const float* __restrict__ x, const float* __restrict__ mean,
    const float* __restrict__ stdv, const float* __restrict__ bdec)
{
    int idx = blockIdx.x * 256 + threadIdx.x;
    int d = idx & 255;
    float a = (x[idx] - mean[d]) / stdv[d] - bdec[d];
    g_xc[idx] = a;
    g_A[idx] = __float2half(a);
}

__global__ void __launch_bounds__(256) prep_w_kernel(const float* __restrict__ Wenc)
{
    int idx = blockIdx.x * 256 + threadIdx.x;
    g_W[idx] = __float2half(Wenc[idx]);
}

__global__ void transpose_wdec(const float* __restrict__ Wdec)
{
    __shared__ float tile[32][33];
    int n = blockIdx.x * 32 + threadIdx.x;
    int d = blockIdx.y * 32 + threadIdx.y;
    tile[threadIdx.y][threadIdx.x] = Wdec[(size_t)d * NF + n];
    __syncthreads();
    int n2 = blockIdx.x * 32 + threadIdx.y;
    int d2 = blockIdx.y * 32 + threadIdx.x;
    g_WdecT[(size_t)n2 * DIM + d2] = tile[threadIdx.x][threadIdx.y];
}

// ===========================================================================
// mma.sync fp16 GEMM: hpre = a0*w0 + benc over 4 K64-chunks.
// CTA tile 128x128, warps 4(M)x2(N), 3-stage cp.async, fully unrolled.
// Epilogue also emits packed 16-bit selection keys (g_hkey).
// ===========================================================================
#define GM 128
#define GN 128
#define NCH 4
#define ATILE (GM * 128)             // 16384 B
#define BTILE (GN * 128)             // 16384 B
#define STAGE (ATILE + BTILE)        // 32768 B
#define DSMEM (3 * STAGE)            // 98304 B

__global__ void __launch_bounds__(256, 2) gemm_kernel(
    const float* __restrict__ benc, float* __restrict__ hpre)
{
    extern __shared__ char dsm[];
    const uint32_t sb = smem_u32(dsm);
    const int tid = threadIdx.x;
    const int wid = tid >> 5, lane = tid & 31;
    const int wm = wid & 3;          // 0..3  (M)
    const int wn = wid >> 2;         // 0..1  (N)

    const int m0 = blockIdx.y * GM;
    const int n0 = blockIdx.x * GN;
    const char* Abase = (const char*)g_A + (size_t)m0 * (KPA * 2);
    const char* Bbase = (const char*)g_W + (size_t)n0 * (KPW * 2);

    // 128B chunk-rows; 16B piece i of row r lands at piece (i ^ (r&7))
    auto load_chunk = [&](int c, uint32_t stagebase) {
        const char* Ag = Abase + c * 128;
#pragma unroll
        for (int q = 0; q < 4; q++) {
            int p = tid + 256 * q; int row = p >> 3, i = p & 7;
            uint32_t sw = (uint32_t)(row * 128) + (uint32_t)((i ^ (row & 7)) * 16);
            asm volatile("cp.async.cg.shared.global [%0], [%1], 16;"
                :: "r"(stagebase + sw), "l"(Ag + (size_t)row * (KPA * 2) + i * 16));
        }
        const char* Bg = Bbase + c * 128;
        const uint32_t bb = stagebase + ATILE;
#pragma unroll
        for (int q = 0; q < 4; q++) {
            int p = tid + 256 * q; int row = p >> 3, i = p & 7;
            uint32_t sw = (uint32_t)(row * 128) + (uint32_t)((i ^ (row & 7)) * 16);
            asm volatile("cp.async.cg.shared.global [%0], [%1], 16;"
                :: "r"(bb + sw), "l"(Bg + (size_t)row * (KPW * 2) + i * 16));
        }
    };

    load_chunk(0, sb);
    asm volatile("cp.async.commit_group;" ::: "memory");
    load_chunk(1, sb + STAGE);
    asm volatile("cp.async.commit_group;" ::: "memory");

    float acc[2][8][4];
#pragma unroll
    for (int a = 0; a < 2; a++)
#pragma unroll
        for (int b = 0; b < 8; b++)
#pragma unroll
            for (int cc = 0; cc < 4; cc++) acc[a][b][cc] = 0.f;

#pragma unroll
    for (int c = 0; c < NCH; c++) {
        if (c < NCH - 1) { asm volatile("cp.async.wait_group 1;" ::: "memory"); }
        else             { asm volatile("cp.async.wait_group 0;" ::: "memory"); }
        __syncthreads();
        if (c + 2 < NCH) {
            load_chunk(c + 2, sb + ((c + 2) % 3) * STAGE);
            asm volatile("cp.async.commit_group;" ::: "memory");
        }

        const uint32_t As = sb + (c % 3) * STAGE;
        const uint32_t Bs = As + ATILE;

#pragma unroll
        for (int ks = 0; ks < 4; ks++) {          // 4 x k16 per 64-chunk
            uint32_t aF[2][4], bF[8][2];
#pragma unroll
            for (int mt = 0; mt < 2; mt++) {
                int row = wm * 32 + mt * 16 + (lane & 15);
                int i = ks * 2 + (lane >> 4);
                uint32_t addr = As + row * 128 + ((i ^ (row & 7)) * 16);
                asm volatile("ldmatrix.sync.aligned.m8n8.x4.shared.b16 {%0,%1,%2,%3}, [%4];"
                    : "=r"(aF[mt][0]), "=r"(aF[mt][1]), "=r"(aF[mt][2]), "=r"(aF[mt][3])
                    : "r"(addr));
            }
#pragma unroll
            for (int nt4 = 0; nt4 < 4; nt4++) {
                int row = wn * 64 + nt4 * 16 + (lane & 15);
                int i = ks * 2 + (lane >> 4);
                uint32_t addr = Bs + row * 128 + ((i ^ (row & 7)) * 16);
                uint32_t r0, r1, r2, r3;
                asm volatile("ldmatrix.sync.aligned.m8n8.x4.shared.b16 {%0,%1,%2,%3}, [%4];"
                    : "=r"(r0), "=r"(r1), "=r"(r2), "=r"(r3) : "r"(addr));
                bF[nt4 * 2][0] = r0;  bF[nt4 * 2][1] = r2;
                bF[nt4 * 2 + 1][0] = r1; bF[nt4 * 2 + 1][1] = r3;
            }
#pragma unroll
            for (int mt = 0; mt < 2; mt++)
#pragma unroll
                for (int nt = 0; nt < 8; nt++)
                    asm volatile(
                        "mma.sync.aligned.m16n8k16.row.col.f32.f16.f16.f32 "
                        "{%0,%1,%2,%3}, {%4,%5,%6,%7}, {%8,%9}, {%0,%1,%2,%3};"
                        : "+f"(acc[mt][nt][0]), "+f"(acc[mt][nt][1]),
                          "+f"(acc[mt][nt][2]), "+f"(acc[mt][nt][3])
                        : "r"(aF[mt][0]), "r"(aF[mt][1]), "r"(aF[mt][2]), "r"(aF[mt][3]),
                          "r"(bF[nt][0]), "r"(bF[nt][1]));
        }
    }

    // Epilogue: +b_enc, write h_pre (fp32) and packed 16-bit keys
    const int g = lane >> 2, tg = lane & 3;
#pragma unroll
    for (int mt = 0; mt < 2; mt++) {
        const int m = m0 + wm * 32 + mt * 16 + g;
#pragma unroll
        for (int nt = 0; nt < 8; nt++) {
            const int n = n0 + wn * 64 + nt * 8 + tg * 2;
            float2 be = *(const float2*)(benc + n);
            float2 o0, o1;
            o0.x = acc[mt][nt][0] + be.x; o0.y = acc[mt][nt][1] + be.y;
            o1.x = acc[mt][nt][2] + be.x; o1.y = acc[mt][nt][3] + be.y;
            *(float2*)(hpre + (size_t)m * NF + n) = o0;
            *(float2*)(hpre + (size_t)(m + 8) * NF + n) = o1;
            *(uint32_t*)(g_hkey + (size_t)m * NF + n) =
                key16(o0.x) | (key16(o0.y) << 16);
            *(uint32_t*)(g_hkey + (size_t)(m + 8) * NF + n) =
                key16(o1.x) | (key16(o1.y) << 16);
        }
    }
}

// ===========================================================================
// Top-K with EXACT selection, reading only the 16-bit key sidecar (8 KB/row).
// Plain shared histogram; pass 1 positives-only with sentinel fallback; cut
// lowered one bin; candidates recomputed exactly in fp32 vs W_enc; full
// h_sparse row built in smem and streamed out.
// ===========================================================================
#define CCAP 96
#define BSENT 0xFFFFFFFFu

__global__ void __launch_bounds__(256) topk_decode_kernel(
    const float* __restrict__ Wenc,
    const float* __restrict__ benc,
    const float* __restrict__ bdec,
    float* __restrict__ hsp,
    float* __restrict__ xhat)
{
    __shared__ float srow[NF];          // 16 KB: full h_sparse row
    __shared__ unsigned hist[256];
    __shared__ float sxc[256];
    __shared__ unsigned sh_byte, sh_excl;
    __shared__ int sh_c;
    __shared__ int   cidx[CCAP];
    __shared__ float hex[CCAP];
    __shared__ int   sseli[TOPK];
    __shared__ float sselv[TOPK];

    const int row = blockIdx.x;
    const int tid = threadIdx.x;
    const int wid = tid >> 5, lane = tid & 31;

    sxc[tid] = g_xc[(size_t)row * DIM + tid];

    // zero the smem h_sparse row
    {
        const float4 z4 = make_float4(0.f, 0.f, 0.f, 0.f);
        float4* s4 = (float4*)srow;
#pragma unroll
        for (int j = 0; j < 4; j++) s4[tid + 256 * j] = z4;
    }

    // load 16 keys packed in 8 uints; uint j covers cols
    //   (tid<<3) + ((j>>2)<<11) + ((j&3)<<1) + {0,1}   (lo half = even col)
    uint32_t pk[8];
    {
        const uint4* kp4 = (const uint4*)(g_hkey + (size_t)row * NF) + tid;
        uint4 t0 = kp4[0];
        uint4 t1 = kp4[256];
        pk[0] = t0.x; pk[1] = t0.y; pk[2] = t0.z; pk[3] = t0.w;
        pk[4] = t1.x; pk[5] = t1.y; pk[6] = t1.z; pk[7] = t1.w;
    }

    unsigned rem = TOPK;
    unsigned prefix = 0;

    // find the 8-bit bin of the rem-th largest in hist[] (from-the-top scan)
    auto scan_select = [&]() {
        __syncthreads();
        if (tid < 32) {
            unsigned h[8], tot = 0;
#pragma unroll
            for (int k = 0; k < 8; k++) { h[k] = hist[tid * 8 + k]; tot += h[k]; }
            unsigned suf = tot;
#pragma unroll
            for (int o = 1; o < 32; o <<= 1) {
                unsigned u = __shfl_down_sync(0xffffffffu, suf, o);
                if (tid + o < 32) suf += u;
            }
            unsigned excl = suf - tot;
#pragma unroll
            for (int k = 7; k >= 0; k--) {
                unsigned incl = excl + h[k];
                if (excl < rem && incl >= rem) { sh_byte = (unsigned)(tid * 8 + k); sh_excl = excl; }
                excl = incl;
            }
        }
        __syncthreads();
    };

    // ---- pass 1: key bits [15:8], positives only (k16 >= 0x8000) ----
    hist[tid] = 0;
    if (tid == 0) sh_byte = BSENT;
    __syncthreads();
#pragma unroll
    for (int j = 0; j < 8; j++) {
        unsigned lo = pk[j] & 0xFFFFu, hi = pk[j] >> 16;
        if (lo & 0x8000u) atomicAdd(&hist[lo >> 8], 1u);
        if (hi & 0x8000u) atomicAdd(&hist[hi >> 8], 1u);
    }
    scan_select();
    if (sh_byte == BSENT) {
        // rare fallback: fewer than TOPK positive values in this row
        __syncthreads();
        hist[tid] = 0;
        __syncthreads();
#pragma unroll
        for (int j = 0; j < 8; j++) {
            atomicAdd(&hist[(pk[j] & 0xFFFFu) >> 8], 1u);
            atomicAdd(&hist[pk[j] >> 24], 1u);
        }
        scan_select();
    }
    prefix = sh_byte;
    rem -= sh_excl;
    __syncthreads();

    // ---- pass 2: key bits [7:0] among prefix matches ----
    hist[tid] = 0;
    if (tid == 0) sh_c = 0;
    __syncthreads();
#pragma unroll
    for (int j = 0; j < 8; j++) {
        unsigned lo = pk[j] & 0xFFFFu, hi = pk[j] >> 16;
        if ((lo >> 8) == prefix) atomicAdd(&hist[lo & 255u], 1u);
        if ((hi >> 8) == prefix) atomicAdd(&hist[hi & 255u], 1u);
    }
    scan_select();
    unsigned cut = (prefix << 8) | sh_byte;
    cut = (cut > 0) ? cut - 1 : 0;                   // one-bin safety margin

    // ---- gather candidates (all keys >= lowered cut) ----
#pragma unroll
    for (int j = 0; j < 8; j++) {
        unsigned lo = pk[j] & 0xFFFFu, hi = pk[j] >> 16;
        int colbase = (tid << 3) + ((j >> 2) << 11) + ((j & 3) << 1);
        if (lo >= cut) {
            int p = atomicAdd(&sh_c, 1);
            if (p < CCAP) cidx[p] = colbase;
        }
        if (hi >= cut) {
            int p = atomicAdd(&sh_c, 1);
            if (p < CCAP) cidx[p] = colbase + 1;
        }
    }
    __syncthreads();
    const int C = (sh_c < CCAP) ? sh_c : CCAP;

    // ---- exact fp32 recompute of candidate dots ----
    for (int j = wid; j < C; j += 8) {
        const float* wr = Wenc + (size_t)cidx[j] * DIM;
        float p = 0.f;
#pragma unroll
        for (int d = 0; d < DIM; d += 32) p = fmaf(sxc[d + lane], wr[d + lane], p);
#pragma unroll
        for (int o = 16; o > 0; o >>= 1) p += __shfl_xor_sync(0xffffffffu, p, o);
        if (lane == 0) hex[j] = p + benc[cidx[j]];
    }
    __syncthreads();

    // ---- rank (value desc, index asc), select top-32, scatter into smem row ----
    if (tid < C) {
        const float my = hex[tid];
        const int myi = cidx[tid];
        int rank = 0;
        for (int j = 0; j < C; j++) {
            float h = hex[j];
            rank += (h > my) || (h == my && cidx[j] < myi);
        }
        if (rank < TOPK) {
            sselv[rank] = my;
            sseli[rank] = myi;
            srow[myi] = my;
        }
    }
    __syncthreads();

    // ---- stream the full h_sparse row out (streaming stores) ----
    {
        float4* hp4 = (float4*)(hsp + (size_t)row * NF);
        const float4* s4 = (const float4*)srow;
#pragma unroll
        for (int j = 0; j < 4; j++) __stcs(hp4 + tid + 256 * j, s4[tid + 256 * j]);
    }

    // ---- sparse decode from exact values ----
    float acc = bdec[tid];
#pragma unroll
    for (int j = 0; j < TOPK; j++)
        acc = fmaf(sselv[j], g_WdecT[(size_t)sseli[j] * DIM + tid], acc);
    xhat[(size_t)row * DIM + tid] = acc;
}

// ===========================================================================
extern "C" void kernel_launch(void* const* d_in, const int* in_sizes, int n_in,
                              void* d_out, int out_size)
{
    const float* x    = (const float*)d_in[0];
    const float* Wenc = (const float*)d_in[1];
    const float* benc = (const float*)d_in[2];
    const float* Wdec = (const float*)d_in[3];
    const float* bdec = (const float*)d_in[4];
    const float* mean = (const float*)d_in[5];
    const float* stdv = (const float*)d_in[6];

    float* out  = (float*)d_out;
    float* xhat = out;                               // (B, D)
    float* hsp  = out + (size_t)BATCH * DIM;         // (B, N)
    float* hpre = hsp + (size_t)BATCH * NF;          // (B, N)

    prep_a_kernel<<<BATCH * DIM / 256, 256>>>(x, mean, stdv, bdec);
    prep_w_kernel<<<NF * DIM / 256, 256>>>(Wenc);

    dim3 tb(32, 32);
    dim3 tg(NF / 32, DIM / 32);
    transpose_wdec<<<tg, tb>>>(Wdec);

    cudaFuncSetAttribute(gemm_kernel,
                         cudaFuncAttributeMaxDynamicSharedMemorySize, DSMEM);
    dim3 gg(NF / GN, BATCH / GM);
    gemm_kernel<<<gg, 256, DSMEM>>>(benc, hpre);

    topk_decode_kernel<<<BATCH, 256>>>(Wenc, benc, bdec, hsp, xhat);
}